// round 8
// baseline (speedup 1.0000x reference)
#include <cuda_runtime.h>
#include <cuda_fp16.h>
#include <math.h>

// Problem constants
#define kB 2
#define kS 2048
#define kE 1024
#define kH 16
#define kD 64
#define kBH (kB * kH)
#define kScale 0.125f
#define kLN1e4 9.210340371976184f

// Scratch (device globals: allocation-free)
static __device__ __half g_qh[kBH * kS * kD];   // [bh][s][d] (rope+scale)
static __device__ __half g_kh[kBH * kS * kD];   // [bh][s][d] (rope)
static __device__ __half g_vth[kBH * kD * kS];  // [bh][d][s] (transposed V)
static __device__ __half g_ctxh[kB * kS * kE];  // [b][s][h*64+d]

// ---------------- helpers ----------------
__device__ __forceinline__ unsigned packh2(float lo, float hi) {
    __half2 h = __floats2half2_rn(lo, hi);
    return *(unsigned*)&h;
}
__device__ __forceinline__ unsigned smem_u32(const void* p) {
    unsigned r;
    asm("{ .reg .u64 t; cvta.to.shared.u64 t, %1; cvt.u32.u64 %0, t; }"
        : "=r"(r) : "l"(p));
    return r;
}
__device__ __forceinline__ void ldsm4(unsigned* f, unsigned addr) {
    asm volatile("ldmatrix.sync.aligned.m8n8.x4.shared.b16 {%0,%1,%2,%3}, [%4];"
                 : "=r"(f[0]), "=r"(f[1]), "=r"(f[2]), "=r"(f[3]) : "r"(addr));
}
__device__ __forceinline__ void cp16(void* dst, const void* src) {
    asm volatile("cp.async.cg.shared.global [%0], [%1], 16;" ::
                     "r"(smem_u32(dst)), "l"(src) : "memory");
}
#define CP_COMMIT() asm volatile("cp.async.commit_group;" ::: "memory")
#define CP_WAIT(n) asm volatile("cp.async.wait_group %0;" :: "n"(n) : "memory")

// D(16x8,f32) += A(16x16,f16) * B(16x8,f16)
__device__ __forceinline__ void mma16h(float* c, const unsigned* a, unsigned b0,
                                       unsigned b1) {
    asm volatile(
        "mma.sync.aligned.m16n8k16.row.col.f32.f16.f16.f32 "
        "{%0,%1,%2,%3}, {%4,%5,%6,%7}, {%8,%9}, {%0,%1,%2,%3};"
        : "+f"(c[0]), "+f"(c[1]), "+f"(c[2]), "+f"(c[3])
        : "r"(a[0]), "r"(a[1]), "r"(a[2]), "r"(a[3]), "r"(b0), "r"(b1));
}

// ---------------- fp16 tensor-core GEMM: out[m,n] = sum_k A[m,k]*W[n,k] -------
// BM=128, BN=128, BK=32, double-buffered. 256 threads = 8 warps (2m x 4n),
// warp tile 64x32.  __launch_bounds__(256, 2) caps regs at 128 so 2 CTAs/SM fit.
// mode 0: A=query(f32), W=w_qkv -> g_qh/g_kh/g_vth (RoPE fused).
// mode 1: A=g_ctxh(f16), W=w_out -> out(f32).
#define GBK 32
#define GPADH 40  // halves per row (32 data + 8 pad); 80B stride, conflict-free
__global__ __launch_bounds__(256, 2) void gemm_h(const float* __restrict__ Ain,
                                                 const float* __restrict__ W,
                                                 float* __restrict__ out, int mode) {
    __shared__ __half As[2][128][GPADH];
    __shared__ __half Ws[2][128][GPADH];

    const int t = threadIdx.x;
    const int w = t >> 5, lane = t & 31;
    const int r = lane >> 2, q = lane & 3;
    const int wm = w >> 2, wn = w & 3;
    const int m0 = blockIdx.x * 128;
    const int n0 = blockIdx.y * 128;

    const int row = t >> 1;          // 0..127
    const int seg = (t & 1) * 16;    // halves within BK

    float c[4][4][4];
#pragma unroll
    for (int i = 0; i < 4; i++)
#pragma unroll
        for (int j = 0; j < 4; j++)
#pragma unroll
            for (int v = 0; v < 4; v++) c[i][j][v] = 0.f;

    const float* Af = Ain + (size_t)(m0 + row) * kE + seg;       // mode 0
    const __half* Ah = g_ctxh + (size_t)(m0 + row) * kE + seg;   // mode 1
    const float* Wf = W + (size_t)(n0 + row) * kE + seg;

    // staged registers for next chunk
    float4 fa[4], fw[4];
    uint4 ua[2];
    if (mode == 0) {
#pragma unroll
        for (int i = 0; i < 4; i++) fa[i] = *(const float4*)(Af + 4 * i);
    } else {
        ua[0] = *(const uint4*)(Ah);
        ua[1] = *(const uint4*)(Ah + 8);
    }
#pragma unroll
    for (int i = 0; i < 4; i++) fw[i] = *(const float4*)(Wf + 4 * i);

    // store stage 0
    {
        if (mode == 0) {
            unsigned tmp[8];
#pragma unroll
            for (int i = 0; i < 4; i++) {
                tmp[2 * i] = packh2(fa[i].x, fa[i].y);
                tmp[2 * i + 1] = packh2(fa[i].z, fa[i].w);
            }
            *(uint4*)&As[0][row][seg] = *(uint4*)&tmp[0];
            *(uint4*)&As[0][row][seg + 8] = *(uint4*)&tmp[4];
        } else {
            *(uint4*)&As[0][row][seg] = ua[0];
            *(uint4*)&As[0][row][seg + 8] = ua[1];
        }
        unsigned tw[8];
#pragma unroll
        for (int i = 0; i < 4; i++) {
            tw[2 * i] = packh2(fw[i].x, fw[i].y);
            tw[2 * i + 1] = packh2(fw[i].z, fw[i].w);
        }
        *(uint4*)&Ws[0][row][seg] = *(uint4*)&tw[0];
        *(uint4*)&Ws[0][row][seg + 8] = *(uint4*)&tw[4];
    }
    __syncthreads();

    // ldmatrix lane addresses (stage 0)
    const unsigned stageSz = 128 * GPADH * 2;  // bytes
    unsigned aoff[4], woff[2];
#pragma unroll
    for (int mt = 0; mt < 4; mt++)
        aoff[mt] = smem_u32(&As[0][wm * 64 + mt * 16 + (lane & 15)][(lane >> 4) * 8]);
#pragma unroll
    for (int ng = 0; ng < 2; ng++)
        woff[ng] = smem_u32(&Ws[0][wn * 32 + ng * 16 + (lane & 15)][(lane >> 4) * 8]);

    const int NIT = kE / GBK;  // 32
    for (int it = 0; it < NIT; it++) {
        const int cur = it & 1;
        if (it + 1 < NIT) {
            const int k0 = (it + 1) * GBK;
            if (mode == 0) {
#pragma unroll
                for (int i = 0; i < 4; i++) fa[i] = *(const float4*)(Af + k0 + 4 * i);
            } else {
                ua[0] = *(const uint4*)(Ah + k0);
                ua[1] = *(const uint4*)(Ah + k0 + 8);
            }
#pragma unroll
            for (int i = 0; i < 4; i++) fw[i] = *(const float4*)(Wf + k0 + 4 * i);
        }
        const unsigned sOf = cur ? stageSz : 0u;
#pragma unroll
        for (int kk = 0; kk < 2; kk++) {  // two k16 steps per BK=32
            unsigned af[4][4], bw[2][4];
#pragma unroll
            for (int mt = 0; mt < 4; mt++) ldsm4(af[mt], aoff[mt] + sOf + kk * 32);
#pragma unroll
            for (int ng = 0; ng < 2; ng++) ldsm4(bw[ng], woff[ng] + sOf + kk * 32);
#pragma unroll
            for (int mt = 0; mt < 4; mt++)
#pragma unroll
                for (int ng = 0; ng < 2; ng++) {
                    mma16h(c[mt][2 * ng], af[mt], bw[ng][0], bw[ng][2]);
                    mma16h(c[mt][2 * ng + 1], af[mt], bw[ng][1], bw[ng][3]);
                }
        }
        if (it + 1 < NIT) {
            const int nxt = cur ^ 1;
            if (mode == 0) {
                unsigned tmp[8];
#pragma unroll
                for (int i = 0; i < 4; i++) {
                    tmp[2 * i] = packh2(fa[i].x, fa[i].y);
                    tmp[2 * i + 1] = packh2(fa[i].z, fa[i].w);
                }
                *(uint4*)&As[nxt][row][seg] = *(uint4*)&tmp[0];
                *(uint4*)&As[nxt][row][seg + 8] = *(uint4*)&tmp[4];
            } else {
                *(uint4*)&As[nxt][row][seg] = ua[0];
                *(uint4*)&As[nxt][row][seg + 8] = ua[1];
            }
            unsigned tw[8];
#pragma unroll
            for (int i = 0; i < 4; i++) {
                tw[2 * i] = packh2(fw[i].x, fw[i].y);
                tw[2 * i + 1] = packh2(fw[i].z, fw[i].w);
            }
            *(uint4*)&Ws[nxt][row][seg] = *(uint4*)&tw[0];
            *(uint4*)&Ws[nxt][row][seg + 8] = *(uint4*)&tw[4];
        }
        __syncthreads();
    }

    // ---------------- epilogue ----------------
    if (mode == 1) {
#pragma unroll
        for (int mt = 0; mt < 4; mt++)
#pragma unroll
            for (int nt = 0; nt < 4; nt++) {
                int mrow = m0 + wm * 64 + mt * 16 + r;
                int col = n0 + wn * 32 + 8 * nt + 2 * q;
                *(float2*)&out[(size_t)mrow * kE + col] =
                    make_float2(c[mt][nt][0], c[mt][nt][1]);
                *(float2*)&out[(size_t)(mrow + 8) * kE + col] =
                    make_float2(c[mt][nt][2], c[mt][nt][3]);
            }
    } else {
        const int which = n0 >> 10;  // 0=q 1=k 2=v (128 | 1024)
#pragma unroll
        for (int mt = 0; mt < 4; mt++)
#pragma unroll
            for (int nt = 0; nt < 4; nt++) {
                int mrow = m0 + wm * 64 + mt * 16 + r;
                int n = n0 + wn * 32 + 8 * nt + 2 * q;
                int h = (n >> 6) & 15;
                int dl = n & 63;
                int b = mrow >> 11, s = mrow & (kS - 1);
                int bh = b * kH + h;
                if (which == 2) {
                    size_t base = ((size_t)(bh * kD + dl)) * kS;
                    g_vth[base + s] = __float2half_rn(c[mt][nt][0]);
                    g_vth[base + kS + s] = __float2half_rn(c[mt][nt][1]);
                    g_vth[base + s + 8] = __float2half_rn(c[mt][nt][2]);
                    g_vth[base + kS + s + 8] = __float2half_rn(c[mt][nt][3]);
                } else {
                    int i = dl >> 1;
                    float inv = expf(-(float)i * (kLN1e4 / 32.0f));
                    float sn0, cs0, sn1, cs1;
                    sincosf((float)s * inv, &sn0, &cs0);
                    sincosf((float)(s + 8) * inv, &sn1, &cs1);
                    float y0 = c[mt][nt][0] * cs0 - c[mt][nt][1] * sn0;
                    float y1 = c[mt][nt][0] * sn0 + c[mt][nt][1] * cs0;
                    float z0 = c[mt][nt][2] * cs1 - c[mt][nt][3] * sn1;
                    float z1 = c[mt][nt][2] * sn1 + c[mt][nt][3] * cs1;
                    __half* dst;
                    if (which == 0) {
                        y0 *= kScale; y1 *= kScale; z0 *= kScale; z1 *= kScale;
                        dst = g_qh;
                    } else {
                        dst = g_kh;
                    }
                    size_t base = ((size_t)(bh * kS + s)) * kD + dl;
                    *(unsigned*)&dst[base] = packh2(y0, y1);
                    *(unsigned*)&dst[base + 8 * kD] = packh2(z0, z1);
                }
            }
    }
}

// ---------------- Flash attention: fp16 MMA + cp.async 2-stage ----------------
// grid: (16 q-tiles, 32 bh). block: 256 threads = 8 warps, 128 q rows, kv tile 64.
__global__ __launch_bounds__(256) void attn_h() {
    __shared__ __half Ks[2][64][72];  // [stage][kv][d]   (also Q staging)
    __shared__ __half Vs[2][64][72];  // [stage][d][kv]

    const int t = threadIdx.x;
    const int w = t >> 5, lane = t & 31;
    const int r = lane >> 2, q = lane & 3;
    const int bh = blockIdx.y;
    const int q0 = blockIdx.x * 128;
    const __half* qb = g_qh + ((size_t)bh * kS + q0) * kD;
    const __half* kb = g_kh + (size_t)bh * kS * kD;
    const __half* vtb = g_vth + (size_t)bh * kD * kS;

    // ---- Stage Q (128 rows) through Ks[0], extract A-frags (4 k16 chunks) ----
    unsigned qa[4][4];
#pragma unroll 1
    for (int half = 0; half < 2; half++) {
        __syncthreads();
        const uint4* qsrc = (const uint4*)(qb + (size_t)half * 64 * kD);
#pragma unroll
        for (int j = 0; j < 2; j++) {
            int idx = t + 256 * j;
            *(uint4*)&Ks[0][idx >> 3][(idx & 7) * 8] = qsrc[idx];
        }
        __syncthreads();
        if ((w >> 2) == half) {
            int m = 16 * (w & 3) + r;
#pragma unroll
            for (int kk = 0; kk < 4; kk++) {
                qa[kk][0] = *(const unsigned*)&Ks[0][m][16 * kk + 2 * q];
                qa[kk][1] = *(const unsigned*)&Ks[0][m + 8][16 * kk + 2 * q];
                qa[kk][2] = *(const unsigned*)&Ks[0][m][16 * kk + 8 + 2 * q];
                qa[kk][3] = *(const unsigned*)&Ks[0][m + 8][16 * kk + 8 + 2 * q];
            }
        }
    }
    __syncthreads();  // Q reads done before prefetch overwrites Ks[0]

    // ---- cp.async prologue: tiles 0 and 1 ----
#pragma unroll 1
    for (int p = 0; p < 2; p++) {
#pragma unroll
        for (int j = 0; j < 2; j++) {
            int idx = t + 256 * j;
            int rw = idx >> 3, c8 = (idx & 7) * 8;
            cp16(&Ks[p][rw][c8], kb + (size_t)(p * 64 + rw) * kD + c8);
            cp16(&Vs[p][rw][c8], vtb + (size_t)rw * kS + p * 64 + c8);
        }
        CP_COMMIT();
    }

    float m0v = -1e30f, m1v = -1e30f, l0 = 0.f, l1 = 0.f;
    float o[8][4];
#pragma unroll
    for (int i = 0; i < 8; i++)
#pragma unroll
        for (int j = 0; j < 4; j++) o[i][j] = 0.f;

    for (int kt = 0; kt < 32; kt++) {
        if (kt == 31) { CP_WAIT(0); } else { CP_WAIT(1); }
        __syncthreads();
        const int st = kt & 1;

        // S = Q K^T  (c[nt]: cols 8nt + {2q,2q+1}; rows 16w+r / +8)
        float c[8][4];
#pragma unroll
        for (int i = 0; i < 8; i++)
#pragma unroll
            for (int j = 0; j < 4; j++) c[i][j] = 0.f;
#pragma unroll
        for (int kk = 0; kk < 4; kk++) {
#pragma unroll
            for (int nt = 0; nt < 8; nt++) {
                unsigned b0 = *(const unsigned*)&Ks[st][8 * nt + r][16 * kk + 2 * q];
                unsigned b1 =
                    *(const unsigned*)&Ks[st][8 * nt + r][16 * kk + 8 + 2 * q];
                mma16h(c[nt], qa[kk], b0, b1);
            }
        }

        // online softmax
        float mt0 = -1e30f, mt1 = -1e30f;
#pragma unroll
        for (int nt = 0; nt < 8; nt++) {
            mt0 = fmaxf(mt0, fmaxf(c[nt][0], c[nt][1]));
            mt1 = fmaxf(mt1, fmaxf(c[nt][2], c[nt][3]));
        }
        mt0 = fmaxf(mt0, __shfl_xor_sync(0xffffffffu, mt0, 1));
        mt0 = fmaxf(mt0, __shfl_xor_sync(0xffffffffu, mt0, 2));
        mt1 = fmaxf(mt1, __shfl_xor_sync(0xffffffffu, mt1, 1));
        mt1 = fmaxf(mt1, __shfl_xor_sync(0xffffffffu, mt1, 2));
        float mn0 = fmaxf(m0v, mt0), mn1 = fmaxf(m1v, mt1);
        float cor0 = __expf(m0v - mn0), cor1 = __expf(m1v - mn1);
        m0v = mn0; m1v = mn1;
        float rs0 = 0.f, rs1 = 0.f;
#pragma unroll
        for (int nt = 0; nt < 8; nt++) {
            c[nt][0] = __expf(c[nt][0] - mn0); rs0 += c[nt][0];
            c[nt][1] = __expf(c[nt][1] - mn0); rs0 += c[nt][1];
            c[nt][2] = __expf(c[nt][2] - mn1); rs1 += c[nt][2];
            c[nt][3] = __expf(c[nt][3] - mn1); rs1 += c[nt][3];
        }
        rs0 += __shfl_xor_sync(0xffffffffu, rs0, 1);
        rs0 += __shfl_xor_sync(0xffffffffu, rs0, 2);
        rs1 += __shfl_xor_sync(0xffffffffu, rs1, 1);
        rs1 += __shfl_xor_sync(0xffffffffu, rs1, 2);
        l0 = l0 * cor0 + rs0;
        l1 = l1 * cor1 + rs1;
#pragma unroll
        for (int nt = 0; nt < 8; nt++) {
            o[nt][0] *= cor0; o[nt][1] *= cor0;
            o[nt][2] *= cor1; o[nt][3] *= cor1;
        }

        // pack P to half2 — A-frags come straight from this lane's registers
        unsigned ph0[8], ph1[8];
#pragma unroll
        for (int nt = 0; nt < 8; nt++) {
            ph0[nt] = packh2(c[nt][0], c[nt][1]);
            ph1[nt] = packh2(c[nt][2], c[nt][3]);
        }

        // O += P V (no shuffles: k16 chunk kk uses cols 16kk+2q & +8 = own regs)
#pragma unroll
        for (int kk = 0; kk < 4; kk++) {
            unsigned a[4] = {ph0[2 * kk], ph1[2 * kk], ph0[2 * kk + 1],
                             ph1[2 * kk + 1]};
#pragma unroll
            for (int nt = 0; nt < 8; nt++) {
                unsigned b0 = *(const unsigned*)&Vs[st][8 * nt + r][16 * kk + 2 * q];
                unsigned b1 =
                    *(const unsigned*)&Vs[st][8 * nt + r][16 * kk + 8 + 2 * q];
                mma16h(o[nt], a, b0, b1);
            }
        }

        __syncthreads();  // stage st fully consumed
        if (kt + 2 < 32) {
            const int p = kt + 2;
#pragma unroll
            for (int j = 0; j < 2; j++) {
                int idx = t + 256 * j;
                int rw = idx >> 3, c8 = (idx & 7) * 8;
                cp16(&Ks[st][rw][c8], kb + (size_t)(p * 64 + rw) * kD + c8);
                cp16(&Vs[st][rw][c8], vtb + (size_t)rw * kS + p * 64 + c8);
            }
            CP_COMMIT();
        }
    }

    // epilogue: normalize, store ctx as half [b][s][h*64+d]
    float il0 = 1.f / l0, il1 = 1.f / l1;
    const int b = bh >> 4, h = bh & 15;
    const int row0 = q0 + 16 * w + r;
    __half* dst = g_ctxh + ((size_t)(b * kS + row0)) * kE + h * kD;
#pragma unroll
    for (int nt = 0; nt < 8; nt++) {
        *(unsigned*)&dst[8 * nt + 2 * q] = packh2(o[nt][0] * il0, o[nt][1] * il0);
        *(unsigned*)&dst[8 * kE + 8 * nt + 2 * q] =
            packh2(o[nt][2] * il1, o[nt][3] * il1);
    }
}

extern "C" void kernel_launch(void* const* d_in, const int* in_sizes, int n_in,
                              void* d_out, int out_size) {
    const float* query = (const float*)d_in[0];
    // d_in[1] (key), d_in[2] (value) are unused by the reference computation
    const float* w_qkv = (const float*)d_in[3];
    const float* w_out = (const float*)d_in[4];
    float* out = (float*)d_out;

    gemm_h<<<dim3(32, 24), 256>>>(query, w_qkv, nullptr, 0);
    attn_h<<<dim3(16, 32), 256>>>();
    gemm_h<<<dim3(32, 8), 256>>>(nullptr, w_out, out, 1);
}

// round 10
// speedup vs baseline: 1.5181x; 1.5181x over previous
#include <cuda_runtime.h>
#include <cuda_fp16.h>
#include <math.h>

// Problem constants
#define kB 2
#define kS 2048
#define kE 1024
#define kH 16
#define kD 64
#define kBH (kB * kH)
#define kScale 0.125f
#define kLN1e4 9.210340371976184f

// Scratch (device globals: allocation-free)
static __device__ __half g_ah[kB * kS * kE];     // query in fp16
static __device__ __half g_wh[3 * kE * kE];      // w_qkv in fp16
static __device__ __half g_woh[kE * kE];         // w_out in fp16
static __device__ __half g_qh[kBH * kS * kD];    // [bh][s][d] (rope+scale)
static __device__ __half g_kh[kBH * kS * kD];    // [bh][s][d] (rope)
static __device__ __half g_vth[kBH * kD * kS];   // [bh][d][s] (transposed V)
static __device__ __half g_ctxh[kB * kS * kE];   // [b][s][h*64+d]

// ---------------- helpers ----------------
__device__ __forceinline__ unsigned packh2(float lo, float hi) {
    __half2 h = __floats2half2_rn(lo, hi);
    return *(unsigned*)&h;
}
__device__ __forceinline__ unsigned smem_u32(const void* p) {
    unsigned r;
    asm("{ .reg .u64 t; cvta.to.shared.u64 t, %1; cvt.u32.u64 %0, t; }"
        : "=r"(r) : "l"(p));
    return r;
}
__device__ __forceinline__ void ldsm4(unsigned* f, unsigned addr) {
    asm volatile("ldmatrix.sync.aligned.m8n8.x4.shared.b16 {%0,%1,%2,%3}, [%4];"
                 : "=r"(f[0]), "=r"(f[1]), "=r"(f[2]), "=r"(f[3]) : "r"(addr));
}
__device__ __forceinline__ void cp16(void* dst, const void* src) {
    asm volatile("cp.async.cg.shared.global [%0], [%1], 16;" ::
                     "r"(smem_u32(dst)), "l"(src) : "memory");
}
#define CP_COMMIT() asm volatile("cp.async.commit_group;" ::: "memory")
#define CP_WAIT(n) asm volatile("cp.async.wait_group %0;" :: "n"(n) : "memory")

// D(16x8,f32) += A(16x16,f16) * B(16x8,f16)
__device__ __forceinline__ void mma16h(float* c, const unsigned* a, unsigned b0,
                                       unsigned b1) {
    asm volatile(
        "mma.sync.aligned.m16n8k16.row.col.f32.f16.f16.f32 "
        "{%0,%1,%2,%3}, {%4,%5,%6,%7}, {%8,%9}, {%0,%1,%2,%3};"
        : "+f"(c[0]), "+f"(c[1]), "+f"(c[2]), "+f"(c[3])
        : "r"(a[0]), "r"(a[1]), "r"(a[2]), "r"(a[3]), "r"(b0), "r"(b1));
}

// ---------------- f32 -> f16 convert (one-shot, elementwise) ----------------
__global__ void cvt_h(const float* __restrict__ src, __half* __restrict__ dst) {
    int i = blockIdx.x * 256 + threadIdx.x;  // one float4 per thread, exact grids
    float4 v = ((const float4*)src)[i];
    uint2 p = make_uint2(packh2(v.x, v.y), packh2(v.z, v.w));
    *(uint2*)&dst[4 * i] = p;
}

// ---------------- fp16 GEMM, cp.async 2-stage: out[m,n]=sum_k A[m,k]*W[n,k] ---
// BM=128, BN=128, BK=32. 256 threads = 8 warps (2m x 4n), warp tile 64x32.
// mode 0: A=g_ah, W=g_wh -> g_qh/g_kh/g_vth (RoPE fused).
// mode 1: A=g_ctxh, W=g_woh -> out (f32).
#define GBK 32
#define GPADH 40  // halves per row (32 data + 8 pad); 80B stride
__global__ __launch_bounds__(256, 2) void gemm_h(const __half* __restrict__ A,
                                                 const __half* __restrict__ W,
                                                 float* __restrict__ out, int mode) {
    __shared__ __half As[2][128][GPADH];
    __shared__ __half Ws[2][128][GPADH];

    const int t = threadIdx.x;
    const int w = t >> 5, lane = t & 31;
    const int r = lane >> 2, q = lane & 3;
    const int wm = w >> 2, wn = w & 3;
    const int m0 = blockIdx.x * 128;
    const int n0 = blockIdx.y * 128;

    float c[4][4][4];
#pragma unroll
    for (int i = 0; i < 4; i++)
#pragma unroll
        for (int j = 0; j < 4; j++)
#pragma unroll
            for (int v = 0; v < 4; v++) c[i][j][v] = 0.f;

    const __half* Ab = A + (size_t)m0 * kE;
    const __half* Wb = W + (size_t)n0 * kE;

    // cp.async tile loader: 128 rows x 32 halves = 512 x 16B chunks per matrix;
    // thread t does chunks t and t+256.  row = i>>2, col = (i&3)*8 halves.
    const int r0 = t >> 2, c0 = (t & 3) * 8;
    const int r1 = (t + 256) >> 2, c1 = ((t + 256) & 3) * 8;

#pragma unroll 1
    for (int p = 0; p < 2; p++) {
        cp16(&As[p][r0][c0], Ab + (size_t)r0 * kE + p * GBK + c0);
        cp16(&As[p][r1][c1], Ab + (size_t)r1 * kE + p * GBK + c1);
        cp16(&Ws[p][r0][c0], Wb + (size_t)r0 * kE + p * GBK + c0);
        cp16(&Ws[p][r1][c1], Wb + (size_t)r1 * kE + p * GBK + c1);
        CP_COMMIT();
    }

    // ldmatrix lane addresses (stage 0)
    const unsigned stageSz = 128 * GPADH * 2;  // bytes
    unsigned aoff[4], woff[2];
#pragma unroll
    for (int mt = 0; mt < 4; mt++)
        aoff[mt] = smem_u32(&As[0][wm * 64 + mt * 16 + (lane & 15)][(lane >> 4) * 8]);
#pragma unroll
    for (int ng = 0; ng < 2; ng++)
        woff[ng] = smem_u32(&Ws[0][wn * 32 + ng * 16 + (lane & 15)][(lane >> 4) * 8]);

    const int NIT = kE / GBK;  // 32
    for (int it = 0; it < NIT; it++) {
        if (it == NIT - 1) { CP_WAIT(0); } else { CP_WAIT(1); }
        __syncthreads();
        const unsigned sOf = (it & 1) ? stageSz : 0u;
#pragma unroll
        for (int kk = 0; kk < 2; kk++) {  // two k16 steps per BK=32
            unsigned af[4][4], bw[2][4];
#pragma unroll
            for (int mt = 0; mt < 4; mt++) ldsm4(af[mt], aoff[mt] + sOf + kk * 32);
#pragma unroll
            for (int ng = 0; ng < 2; ng++) ldsm4(bw[ng], woff[ng] + sOf + kk * 32);
#pragma unroll
            for (int mt = 0; mt < 4; mt++)
#pragma unroll
                for (int ng = 0; ng < 2; ng++) {
                    mma16h(c[mt][2 * ng], af[mt], bw[ng][0], bw[ng][2]);
                    mma16h(c[mt][2 * ng + 1], af[mt], bw[ng][1], bw[ng][3]);
                }
        }
        __syncthreads();  // stage fully consumed before refill
        if (it + 2 < NIT) {
            const int st = it & 1;
            const int k0 = (it + 2) * GBK;
            cp16(&As[st][r0][c0], Ab + (size_t)r0 * kE + k0 + c0);
            cp16(&As[st][r1][c1], Ab + (size_t)r1 * kE + k0 + c1);
            cp16(&Ws[st][r0][c0], Wb + (size_t)r0 * kE + k0 + c0);
            cp16(&Ws[st][r1][c1], Wb + (size_t)r1 * kE + k0 + c1);
            CP_COMMIT();
        }
    }

    // ---------------- epilogue ----------------
    if (mode == 1) {
#pragma unroll
        for (int mt = 0; mt < 4; mt++)
#pragma unroll
            for (int nt = 0; nt < 4; nt++) {
                int mrow = m0 + wm * 64 + mt * 16 + r;
                int col = n0 + wn * 32 + 8 * nt + 2 * q;
                *(float2*)&out[(size_t)mrow * kE + col] =
                    make_float2(c[mt][nt][0], c[mt][nt][1]);
                *(float2*)&out[(size_t)(mrow + 8) * kE + col] =
                    make_float2(c[mt][nt][2], c[mt][nt][3]);
            }
    } else {
        const int which = n0 >> 10;  // 0=q 1=k 2=v
#pragma unroll
        for (int mt = 0; mt < 4; mt++)
#pragma unroll
            for (int nt = 0; nt < 4; nt++) {
                int mrow = m0 + wm * 64 + mt * 16 + r;
                int n = n0 + wn * 32 + 8 * nt + 2 * q;
                int h = (n >> 6) & 15;
                int dl = n & 63;
                int b = mrow >> 11, s = mrow & (kS - 1);
                int bh = b * kH + h;
                if (which == 2) {
                    size_t base = ((size_t)(bh * kD + dl)) * kS;
                    g_vth[base + s] = __float2half_rn(c[mt][nt][0]);
                    g_vth[base + kS + s] = __float2half_rn(c[mt][nt][1]);
                    g_vth[base + s + 8] = __float2half_rn(c[mt][nt][2]);
                    g_vth[base + kS + s + 8] = __float2half_rn(c[mt][nt][3]);
                } else {
                    int i = dl >> 1;
                    float inv = expf(-(float)i * (kLN1e4 / 32.0f));
                    float sn0, cs0, sn1, cs1;
                    sincosf((float)s * inv, &sn0, &cs0);
                    sincosf((float)(s + 8) * inv, &sn1, &cs1);
                    float y0 = c[mt][nt][0] * cs0 - c[mt][nt][1] * sn0;
                    float y1 = c[mt][nt][0] * sn0 + c[mt][nt][1] * cs0;
                    float z0 = c[mt][nt][2] * cs1 - c[mt][nt][3] * sn1;
                    float z1 = c[mt][nt][2] * sn1 + c[mt][nt][3] * cs1;
                    __half* dst;
                    if (which == 0) {
                        y0 *= kScale; y1 *= kScale; z0 *= kScale; z1 *= kScale;
                        dst = g_qh;
                    } else {
                        dst = g_kh;
                    }
                    size_t base = ((size_t)(bh * kS + s)) * kD + dl;
                    *(unsigned*)&dst[base] = packh2(y0, y1);
                    *(unsigned*)&dst[base + 8 * kD] = packh2(z0, z1);
                }
            }
    }
}

// ---------------- Flash attention: fp16 MMA + cp.async 2-stage ----------------
// grid: (16 q-tiles, 32 bh). block: 256 threads = 8 warps, 128 q rows, kv tile 64.
__global__ __launch_bounds__(256) void attn_h() {
    __shared__ __half Ks[2][64][72];  // [stage][kv][d]   (also Q staging)
    __shared__ __half Vs[2][64][72];  // [stage][d][kv]

    const int t = threadIdx.x;
    const int w = t >> 5, lane = t & 31;
    const int r = lane >> 2, q = lane & 3;
    const int bh = blockIdx.y;
    const int q0 = blockIdx.x * 128;
    const __half* qb = g_qh + ((size_t)bh * kS + q0) * kD;
    const __half* kb = g_kh + (size_t)bh * kS * kD;
    const __half* vtb = g_vth + (size_t)bh * kD * kS;

    // ---- Stage Q (128 rows) through Ks[0], extract A-frags (4 k16 chunks) ----
    unsigned qa[4][4];
#pragma unroll 1
    for (int half = 0; half < 2; half++) {
        __syncthreads();
        const uint4* qsrc = (const uint4*)(qb + (size_t)half * 64 * kD);
#pragma unroll
        for (int j = 0; j < 2; j++) {
            int idx = t + 256 * j;
            *(uint4*)&Ks[0][idx >> 3][(idx & 7) * 8] = qsrc[idx];
        }
        __syncthreads();
        if ((w >> 2) == half) {
            int m = 16 * (w & 3) + r;
#pragma unroll
            for (int kk = 0; kk < 4; kk++) {
                qa[kk][0] = *(const unsigned*)&Ks[0][m][16 * kk + 2 * q];
                qa[kk][1] = *(const unsigned*)&Ks[0][m + 8][16 * kk + 2 * q];
                qa[kk][2] = *(const unsigned*)&Ks[0][m][16 * kk + 8 + 2 * q];
                qa[kk][3] = *(const unsigned*)&Ks[0][m + 8][16 * kk + 8 + 2 * q];
            }
        }
    }
    __syncthreads();  // Q reads done before prefetch overwrites Ks[0]

    // ---- cp.async prologue: tiles 0 and 1 ----
#pragma unroll 1
    for (int p = 0; p < 2; p++) {
#pragma unroll
        for (int j = 0; j < 2; j++) {
            int idx = t + 256 * j;
            int rw = idx >> 3, c8 = (idx & 7) * 8;
            cp16(&Ks[p][rw][c8], kb + (size_t)(p * 64 + rw) * kD + c8);
            cp16(&Vs[p][rw][c8], vtb + (size_t)rw * kS + p * 64 + c8);
        }
        CP_COMMIT();
    }

    float m0v = -1e30f, m1v = -1e30f, l0 = 0.f, l1 = 0.f;
    float o[8][4];
#pragma unroll
    for (int i = 0; i < 8; i++)
#pragma unroll
        for (int j = 0; j < 4; j++) o[i][j] = 0.f;

    for (int kt = 0; kt < 32; kt++) {
        if (kt == 31) { CP_WAIT(0); } else { CP_WAIT(1); }
        __syncthreads();
        const int st = kt & 1;

        // S = Q K^T
        float c[8][4];
#pragma unroll
        for (int i = 0; i < 8; i++)
#pragma unroll
            for (int j = 0; j < 4; j++) c[i][j] = 0.f;
#pragma unroll
        for (int kk = 0; kk < 4; kk++) {
#pragma unroll
            for (int nt = 0; nt < 8; nt++) {
                unsigned b0 = *(const unsigned*)&Ks[st][8 * nt + r][16 * kk + 2 * q];
                unsigned b1 =
                    *(const unsigned*)&Ks[st][8 * nt + r][16 * kk + 8 + 2 * q];
                mma16h(c[nt], qa[kk], b0, b1);
            }
        }

        // online softmax
        float mt0 = -1e30f, mt1 = -1e30f;
#pragma unroll
        for (int nt = 0; nt < 8; nt++) {
            mt0 = fmaxf(mt0, fmaxf(c[nt][0], c[nt][1]));
            mt1 = fmaxf(mt1, fmaxf(c[nt][2], c[nt][3]));
        }
        mt0 = fmaxf(mt0, __shfl_xor_sync(0xffffffffu, mt0, 1));
        mt0 = fmaxf(mt0, __shfl_xor_sync(0xffffffffu, mt0, 2));
        mt1 = fmaxf(mt1, __shfl_xor_sync(0xffffffffu, mt1, 1));
        mt1 = fmaxf(mt1, __shfl_xor_sync(0xffffffffu, mt1, 2));
        float mn0 = fmaxf(m0v, mt0), mn1 = fmaxf(m1v, mt1);
        float cor0 = __expf(m0v - mn0), cor1 = __expf(m1v - mn1);
        m0v = mn0; m1v = mn1;
        float rs0 = 0.f, rs1 = 0.f;
#pragma unroll
        for (int nt = 0; nt < 8; nt++) {
            c[nt][0] = __expf(c[nt][0] - mn0); rs0 += c[nt][0];
            c[nt][1] = __expf(c[nt][1] - mn0); rs0 += c[nt][1];
            c[nt][2] = __expf(c[nt][2] - mn1); rs1 += c[nt][2];
            c[nt][3] = __expf(c[nt][3] - mn1); rs1 += c[nt][3];
        }
        rs0 += __shfl_xor_sync(0xffffffffu, rs0, 1);
        rs0 += __shfl_xor_sync(0xffffffffu, rs0, 2);
        rs1 += __shfl_xor_sync(0xffffffffu, rs1, 1);
        rs1 += __shfl_xor_sync(0xffffffffu, rs1, 2);
        l0 = l0 * cor0 + rs0;
        l1 = l1 * cor1 + rs1;
#pragma unroll
        for (int nt = 0; nt < 8; nt++) {
            o[nt][0] *= cor0; o[nt][1] *= cor0;
            o[nt][2] *= cor1; o[nt][3] *= cor1;
        }

        // pack P to half2 — A-frags straight from this lane's registers
        unsigned ph0[8], ph1[8];
#pragma unroll
        for (int nt = 0; nt < 8; nt++) {
            ph0[nt] = packh2(c[nt][0], c[nt][1]);
            ph1[nt] = packh2(c[nt][2], c[nt][3]);
        }

        // O += P V
#pragma unroll
        for (int kk = 0; kk < 4; kk++) {
            unsigned a[4] = {ph0[2 * kk], ph1[2 * kk], ph0[2 * kk + 1],
                             ph1[2 * kk + 1]};
#pragma unroll
            for (int nt = 0; nt < 8; nt++) {
                unsigned b0 = *(const unsigned*)&Vs[st][8 * nt + r][16 * kk + 2 * q];
                unsigned b1 =
                    *(const unsigned*)&Vs[st][8 * nt + r][16 * kk + 8 + 2 * q];
                mma16h(o[nt], a, b0, b1);
            }
        }

        __syncthreads();  // stage st fully consumed
        if (kt + 2 < 32) {
            const int p = kt + 2;
#pragma unroll
            for (int j = 0; j < 2; j++) {
                int idx = t + 256 * j;
                int rw = idx >> 3, c8 = (idx & 7) * 8;
                cp16(&Ks[st][rw][c8], kb + (size_t)(p * 64 + rw) * kD + c8);
                cp16(&Vs[st][rw][c8], vtb + (size_t)rw * kS + p * 64 + c8);
            }
            CP_COMMIT();
        }
    }

    // epilogue: normalize, store ctx as half [b][s][h*64+d]
    float il0 = 1.f / l0, il1 = 1.f / l1;
    const int b = bh >> 4, h = bh & 15;
    const int row0 = q0 + 16 * w + r;
    __half* dst = g_ctxh + ((size_t)(b * kS + row0)) * kE + h * kD;
#pragma unroll
    for (int nt = 0; nt < 8; nt++) {
        *(unsigned*)&dst[8 * nt + 2 * q] = packh2(o[nt][0] * il0, o[nt][1] * il0);
        *(unsigned*)&dst[8 * kE + 8 * nt + 2 * q] =
            packh2(o[nt][2] * il1, o[nt][3] * il1);
    }
}

extern "C" void kernel_launch(void* const* d_in, const int* in_sizes, int n_in,
                              void* d_out, int out_size) {
    const float* query = (const float*)d_in[0];
    // d_in[1] (key), d_in[2] (value) are unused by the reference computation
    const float* w_qkv = (const float*)d_in[3];
    const float* w_out = (const float*)d_in[4];
    float* out = (float*)d_out;

    __half* d_ah;   cudaGetSymbolAddress((void**)&d_ah, g_ah);
    __half* d_wh;   cudaGetSymbolAddress((void**)&d_wh, g_wh);
    __half* d_woh;  cudaGetSymbolAddress((void**)&d_woh, g_woh);
    __half* d_ctxh; cudaGetSymbolAddress((void**)&d_ctxh, g_ctxh);

    cvt_h<<<kB * kS * kE / 1024, 256>>>(query, d_ah);
    cvt_h<<<3 * kE * kE / 1024, 256>>>(w_qkv, d_wh);
    cvt_h<<<kE * kE / 1024, 256>>>(w_out, d_woh);
    gemm_h<<<dim3(32, 24), 256>>>(d_ah, d_wh, nullptr, 0);
    attn_h<<<dim3(16, 32), 256>>>();
    gemm_h<<<dim3(32, 8), 256>>>(d_ctxh, d_woh, out, 1);
}